// round 11
// baseline (speedup 1.0000x reference)
#include <cuda_runtime.h>
#include <cuda_bf16.h>
#include <cstdint>

// Problem constants
#define PN 8192      // batch rows
#define PC 1024      // feature dim
#define PS 8192      // negatives (sampled)
#define PUNITS 128000

// ---------------- device scratch (static, allocation-free) ----------------
__device__ __nv_bfloat16 g_X[PN * PC];   // inputs in bf16           (16 MB)
__device__ __nv_bfloat16 g_W[PS * PC];   // gathered sampled rows    (16 MB)
__device__ float g_bcorr[PS];            // bias[sampled] - log(E(sampled))
__device__ float g_true[PN];             // corrected true logits
__device__ float g_rowsum[PN];           // sum_s exp(corrected samp logit)

// ---------------- helpers ----------------
__device__ __forceinline__ float neg_log_expected(int id) {
    float idf = (float)id;
    float p = (logf(idf + 2.0f) - logf(idf + 1.0f)) / logf((float)(PUNITS + 1));
    float e = -expm1f((float)PS * log1pf(-p));
    return -logf(e);
}

__device__ __forceinline__ void ldm_x4(uint32_t (&r)[4], uint32_t saddr) {
    asm volatile("ldmatrix.sync.aligned.m8n8.x4.shared.b16 {%0,%1,%2,%3}, [%4];"
                 : "=r"(r[0]), "=r"(r[1]), "=r"(r[2]), "=r"(r[3])
                 : "r"(saddr));
}

__device__ __forceinline__ void mma_bf16(float (&c)[4], const uint32_t (&a)[4],
                                         const uint32_t b0, const uint32_t b1) {
    asm volatile(
        "mma.sync.aligned.m16n8k16.row.col.f32.bf16.bf16.f32 "
        "{%0,%1,%2,%3}, {%4,%5,%6,%7}, {%8,%9}, {%0,%1,%2,%3};"
        : "+f"(c[0]), "+f"(c[1]), "+f"(c[2]), "+f"(c[3])
        : "r"(a[0]), "r"(a[1]), "r"(a[2]), "r"(a[3]), "r"(b0), "r"(b1));
}

#define CP_ASYNC16(dst, src) \
    asm volatile("cp.async.cg.shared.global [%0], [%1], 16;" :: "r"(dst), "l"(src))

// ---------------- prep: bf16 convert inputs + gather sampled W rows ----------------
__global__ void prep_gather_kernel(const float* __restrict__ inputs,
                                   const int* __restrict__ sampled,
                                   const float* __restrict__ kern) {
    const int total4 = (PN * PC) / 4;
    for (int i = blockIdx.x * blockDim.x + threadIdx.x; i < total4;
         i += gridDim.x * blockDim.x) {
        float4 x = ((const float4*)inputs)[i];
        __nv_bfloat162* dx = (__nv_bfloat162*)g_X + (size_t)i * 2;
        dx[0] = __floats2bfloat162_rn(x.x, x.y);
        dx[1] = __floats2bfloat162_rn(x.z, x.w);

        int s  = i >> 8;
        int c4 = i & 255;
        float4 w = ((const float4*)(kern + ((size_t)sampled[s] << 10)))[c4];
        __nv_bfloat162* dw = (__nv_bfloat162*)g_W + (size_t)i * 2;
        dw[0] = __floats2bfloat162_rn(w.x, w.y);
        dw[1] = __floats2bfloat162_rn(w.z, w.w);
    }
}

// ---------------- prep: sampled bias + correction ----------------
__global__ void prep_bcorr_kernel(const int* __restrict__ sampled,
                                  const float* __restrict__ bias) {
    int s = blockIdx.x * blockDim.x + threadIdx.x;
    if (s < PS) {
        int sid = sampled[s];
        g_bcorr[s] = bias[sid] + neg_log_expected(sid);
    }
}

// ---------------- prep: true logits (fp32) + zero rowsums ----------------
__global__ void prep_true_kernel(const float* __restrict__ inputs,
                                 const int* __restrict__ targets,
                                 const float* __restrict__ kern,
                                 const float* __restrict__ bias) {
    int warp = threadIdx.x >> 5, lane = threadIdx.x & 31;
    int n = blockIdx.x * 8 + warp;
    if (n >= PN) return;
    int tgt = targets[n];
    const float4* xr = (const float4*)(inputs + ((size_t)n << 10));
    const float4* wr = (const float4*)(kern + ((size_t)tgt << 10));
    float d = 0.f;
#pragma unroll
    for (int it = 0; it < 8; ++it) {
        float4 a = xr[lane + it * 32];
        float4 b = wr[lane + it * 32];
        d += a.x * b.x + a.y * b.y + a.z * b.z + a.w * b.w;
    }
#pragma unroll
    for (int o = 16; o; o >>= 1) d += __shfl_down_sync(0xffffffffu, d, o);
    if (lane == 0) {
        g_true[n] = d + bias[tgt] + neg_log_expected(tgt);
        g_rowsum[n] = 0.f;
    }
}

// ---------------- fused GEMM (bf16 mma.sync) + exp epilogue ----------------
// CTA tile 128x128, 4 warps in 2(M) x 2(N), warp tile 64x64.
// K-chunk 64, 3-stage cp.async pipeline, register fragment double-buffering,
// cross-chunk boundary software pipelining (boundary LDFRAG under last MMA).
#define SLD 72                         // smem K stride (64 + 8 pad) in bf16
#define A_STG (128 * SLD * 2)          // 18432 B per operand stage
#define NSTG 3
#define OFF_B    (NSTG * A_STG)        // 55296
#define OFF_SROW (2 * NSTG * A_STG)    // 110592
#define SMEM_BYTES (OFF_SROW + 512)
#define NK (PC / 64)                   // 16 K-chunks

__global__ __launch_bounds__(128, 2) void gemm_exp_kernel(
    const int* __restrict__ targets, const int* __restrict__ sampled) {
    extern __shared__ char smem[];
    float* srow = (float*)(smem + OFF_SROW);

    const int tid = threadIdx.x;
    const int lane = tid & 31, warp = tid >> 5;
    const int wm = warp >> 1, wn = warp & 1;       // 2 x 2 warp grid
    const int bm = blockIdx.y * 128, bn = blockIdx.x * 128;

    float acc[4][8][4];
#pragma unroll
    for (int mi = 0; mi < 4; mi++)
#pragma unroll
        for (int ni = 0; ni < 8; ni++)
#pragma unroll
            for (int e = 0; e < 4; e++) acc[mi][ni][e] = 0.f;

    srow[tid] = 0.f;

    uint32_t sbase;
    asm("{ .reg .u64 t; cvta.to.shared.u64 t, %1; cvt.u32.u64 %0, t; }"
        : "=r"(sbase) : "l"(smem));
    const uint32_t sA = sbase;
    const uint32_t sB = sbase + OFF_B;

    // ldmatrix per-lane address components (within tile)
    const int arow  = wm * 64 + (lane & 7) + 8 * ((lane >> 3) & 1);
    const int acoff = (lane >> 4) * 8;
    const int brow  = wn * 64 + (lane & 7) + 8 * (lane >> 4);
    const int bcoff = ((lane >> 3) & 1) * 8;

    // global->shared: 1024 16B chunks per operand per stage, 8 per thread
    const int r0 = tid >> 3, c0 = tid & 7;   // rows r0 + it*16, it=0..7
    const __nv_bfloat16* Ag = g_X + (size_t)(bm + r0) * PC + c0 * 8;
    const __nv_bfloat16* Bg = g_W + (size_t)(bn + r0) * PC + c0 * 8;
    const uint32_t dA = sA + (uint32_t)(r0 * SLD + c0 * 8) * 2;
    const uint32_t dB = sB + (uint32_t)(r0 * SLD + c0 * 8) * 2;

#define LOAD_STAGE(kt_, so_)                                                   \
    do {                                                                       \
        if ((kt_) < NK) {                                                      \
            uint32_t so = (uint32_t)(so_) * A_STG;                             \
            int ko = (kt_) * 64;                                               \
            _Pragma("unroll")                                                  \
            for (int it = 0; it < 8; ++it) {                                   \
                CP_ASYNC16(dA + so + (uint32_t)(it * 16 * SLD * 2),            \
                           Ag + ko + (size_t)it * 16 * PC);                    \
                CP_ASYNC16(dB + so + (uint32_t)(it * 16 * SLD * 2),            \
                           Bg + ko + (size_t)it * 16 * PC);                    \
            }                                                                  \
        }                                                                      \
        asm volatile("cp.async.commit_group;" ::: "memory");                   \
    } while (0)

    uint32_t afr[2][4][4];
    uint32_t bfr[2][8][2];

#define LDFRAG(buf_, ca_, cb_, ks_)                                            \
    do {                                                                       \
        _Pragma("unroll")                                                      \
        for (int mi = 0; mi < 4; mi++)                                         \
            ldm_x4(afr[buf_][mi], (ca_) +                                      \
                (uint32_t)(((arow + mi * 16) * SLD + (ks_) * 16 + acoff) * 2));\
        _Pragma("unroll")                                                      \
        for (int nb = 0; nb < 4; nb++) {                                       \
            uint32_t r[4];                                                     \
            ldm_x4(r, (cb_) +                                                  \
                (uint32_t)(((brow + nb * 16) * SLD + (ks_) * 16 + bcoff) * 2));\
            bfr[buf_][2 * nb][0] = r[0];                                       \
            bfr[buf_][2 * nb][1] = r[1];                                       \
            bfr[buf_][2 * nb + 1][0] = r[2];                                   \
            bfr[buf_][2 * nb + 1][1] = r[3];                                   \
        }                                                                      \
    } while (0)

#define MMA_GROUP(buf_)                                                        \
    do {                                                                       \
        _Pragma("unroll")                                                      \
        for (int mi = 0; mi < 4; mi++)                                         \
            _Pragma("unroll")                                                  \
            for (int ni = 0; ni < 8; ni++)                                     \
                mma_bf16(acc[mi][ni], afr[buf_][mi], bfr[buf_][ni][0],         \
                         bfr[buf_][ni][1]);                                    \
    } while (0)

    // prologue: stages 0,1 in flight; stage 0 ready; preload ks=0 fragments
    LOAD_STAGE(0, 0);
    LOAD_STAGE(1, 1);
    asm volatile("cp.async.wait_group 1;" ::: "memory");
    __syncthreads();

    int s_cur = 0, s_ld = 2;
    uint32_t ca = sA, cb = sB;
    LDFRAG(0, ca, cb, 0);

#pragma unroll 1
    for (int kt = 0; kt < NK; ++kt) {
        // issue loads for stage kt+2 into buffer s_ld (== stage kt-1, fully
        // consumed — sync at the boundary of iteration kt-1 guarantees it)
        LOAD_STAGE(kt + 2, s_ld);
        s_ld = (s_ld == 2) ? 0 : s_ld + 1;

        LDFRAG(1, ca, cb, 1);
        MMA_GROUP(0);
        LDFRAG(0, ca, cb, 2);
        MMA_GROUP(1);
        LDFRAG(1, ca, cb, 3);
        MMA_GROUP(0);

        // boundary hoisted before the last MMA group: stage kt smem is fully
        // consumed (all its fragments are in registers), so sync + next-chunk
        // ks=0 fragment load run under the cover of MMA_GROUP(1) below.
        if (kt + 1 < NK) {
            asm volatile("cp.async.wait_group 1;" ::: "memory");
            __syncthreads();
            s_cur = (s_cur == 2) ? 0 : s_cur + 1;
            ca = sA + (uint32_t)s_cur * A_STG;
            cb = sB + (uint32_t)s_cur * A_STG;
            LDFRAG(0, ca, cb, 0);
        }

        MMA_GROUP(1);
    }

    // ---- epilogue: corrected logits -> exp -> per-row partial sums ----
    int tg[4][2];
#pragma unroll
    for (int mi = 0; mi < 4; mi++)
#pragma unroll
        for (int h = 0; h < 2; h++)
            tg[mi][h] = targets[bm + wm * 64 + mi * 16 + (lane >> 2) + h * 8];

    float rs[4][2];
#pragma unroll
    for (int mi = 0; mi < 4; mi++) { rs[mi][0] = 0.f; rs[mi][1] = 0.f; }

#pragma unroll
    for (int ni = 0; ni < 8; ni++) {
#pragma unroll
        for (int j = 0; j < 2; j++) {
            int col = bn + wn * 64 + ni * 8 + ((lane & 3) << 1) + j;
            int sid = sampled[col];
            float bc = g_bcorr[col];
#pragma unroll
            for (int mi = 0; mi < 4; mi++) {
#pragma unroll
                for (int h = 0; h < 2; h++) {
                    if (sid != tg[mi][h])
                        rs[mi][h] += __expf(acc[mi][ni][h * 2 + j] + bc);
                }
            }
        }
    }

#pragma unroll
    for (int mi = 0; mi < 4; mi++) {
#pragma unroll
        for (int h = 0; h < 2; h++) {
            float v = rs[mi][h];
            v += __shfl_xor_sync(0xffffffffu, v, 1);
            v += __shfl_xor_sync(0xffffffffu, v, 2);
            if ((lane & 3) == 0)
                atomicAdd(&srow[wm * 64 + mi * 16 + (lane >> 2) + h * 8], v);
        }
    }
    __syncthreads();
    atomicAdd(&g_rowsum[bm + tid], srow[tid]);
}

// ---------------- finalize: per-example loss + mean ----------------
__global__ void finalize_kernel(float* __restrict__ out) {
    __shared__ double sh[32];
    double local = 0.0;
    for (int n = threadIdx.x; n < PN; n += 1024) {
        float t = g_true[n];
        float v = logf(g_rowsum[n] + expf(t)) - t;
        local += (double)v;
    }
#pragma unroll
    for (int o = 16; o; o >>= 1) local += __shfl_down_sync(0xffffffffu, local, o);
    if ((threadIdx.x & 31) == 0) sh[threadIdx.x >> 5] = local;
    __syncthreads();
    if (threadIdx.x < 32) {
        double v = sh[threadIdx.x];
#pragma unroll
        for (int o = 16; o; o >>= 1) v += __shfl_down_sync(0xffffffffu, v, o);
        if (threadIdx.x == 0) out[0] = (float)(v / (double)PN);
    }
}

// ---------------- entry ----------------
extern "C" void kernel_launch(void* const* d_in, const int* in_sizes, int n_in,
                              void* d_out, int out_size) {
    const float* inputs  = (const float*)d_in[0];
    const int*   targets = (const int*)d_in[1];
    const int*   sampled = (const int*)d_in[2];
    const float* kern    = (const float*)d_in[3];
    const float* bias    = (const float*)d_in[4];
    float* out = (float*)d_out;

    static int smem_set = 0;
    if (!smem_set) {
        cudaFuncSetAttribute(gemm_exp_kernel,
                             cudaFuncAttributeMaxDynamicSharedMemorySize, SMEM_BYTES);
        smem_set = 1;
    }

    prep_gather_kernel<<<4096, 256>>>(inputs, sampled, kern);
    prep_bcorr_kernel<<<PS / 256, 256>>>(sampled, bias);
    prep_true_kernel<<<PN / 8, 256>>>(inputs, targets, kern, bias);

    dim3 grid(PS / 128, PN / 128);
    gemm_exp_kernel<<<grid, 128, SMEM_BYTES>>>(targets, sampled);

    finalize_kernel<<<1, 1024>>>(out);
}

// round 12
// speedup vs baseline: 1.0912x; 1.0912x over previous
#include <cuda_runtime.h>
#include <cuda_bf16.h>
#include <cstdint>

// Problem constants
#define PN 8192      // batch rows
#define PC 1024      // feature dim
#define PS 8192      // negatives (sampled)
#define PUNITS 128000

// ---------------- device scratch (static, allocation-free) ----------------
__device__ __nv_bfloat16 g_X[PN * PC];   // inputs in bf16           (16 MB)
__device__ __nv_bfloat16 g_W[PS * PC];   // gathered sampled rows    (16 MB)
__device__ float g_bcorr[PS];            // bias[sampled] - log(E(sampled))
__device__ float g_true[PN];             // corrected true logits
__device__ float g_rowsum[PN];           // sum_s exp(corrected samp logit)

// ---------------- helpers ----------------
__device__ __forceinline__ float neg_log_expected(int id) {
    float idf = (float)id;
    float p = (logf(idf + 2.0f) - logf(idf + 1.0f)) / logf((float)(PUNITS + 1));
    float e = -expm1f((float)PS * log1pf(-p));
    return -logf(e);
}

__device__ __forceinline__ void ldm_x4(uint32_t (&r)[4], uint32_t saddr) {
    asm volatile("ldmatrix.sync.aligned.m8n8.x4.shared.b16 {%0,%1,%2,%3}, [%4];"
                 : "=r"(r[0]), "=r"(r[1]), "=r"(r[2]), "=r"(r[3])
                 : "r"(saddr));
}

__device__ __forceinline__ void mma_bf16(float (&c)[4], const uint32_t (&a)[4],
                                         const uint32_t b0, const uint32_t b1) {
    asm volatile(
        "mma.sync.aligned.m16n8k16.row.col.f32.bf16.bf16.f32 "
        "{%0,%1,%2,%3}, {%4,%5,%6,%7}, {%8,%9}, {%0,%1,%2,%3};"
        : "+f"(c[0]), "+f"(c[1]), "+f"(c[2]), "+f"(c[3])
        : "r"(a[0]), "r"(a[1]), "r"(a[2]), "r"(a[3]), "r"(b0), "r"(b1));
}

#define CP_ASYNC16(dst, src) \
    asm volatile("cp.async.cg.shared.global [%0], [%1], 16;" :: "r"(dst), "l"(src))

// ---------------- prep: bf16 convert + gather + bcorr (fused) ----------------
__global__ void prep_gather_kernel(const float* __restrict__ inputs,
                                   const int* __restrict__ sampled,
                                   const float* __restrict__ kern,
                                   const float* __restrict__ bias) {
    const int gid = blockIdx.x * blockDim.x + threadIdx.x;
    if (gid < PS) {
        int sid = sampled[gid];
        g_bcorr[gid] = bias[sid] + neg_log_expected(sid);
    }
    const int total4 = (PN * PC) / 4;
    for (int i = gid; i < total4; i += gridDim.x * blockDim.x) {
        float4 x = ((const float4*)inputs)[i];
        __nv_bfloat162* dx = (__nv_bfloat162*)g_X + (size_t)i * 2;
        dx[0] = __floats2bfloat162_rn(x.x, x.y);
        dx[1] = __floats2bfloat162_rn(x.z, x.w);

        int s  = i >> 8;
        int c4 = i & 255;
        float4 w = ((const float4*)(kern + ((size_t)sampled[s] << 10)))[c4];
        __nv_bfloat162* dw = (__nv_bfloat162*)g_W + (size_t)i * 2;
        dw[0] = __floats2bfloat162_rn(w.x, w.y);
        dw[1] = __floats2bfloat162_rn(w.z, w.w);
    }
}

// ---------------- prep: true logits (fp32) + zero rowsums ----------------
__global__ void prep_true_kernel(const float* __restrict__ inputs,
                                 const int* __restrict__ targets,
                                 const float* __restrict__ kern,
                                 const float* __restrict__ bias) {
    int warp = threadIdx.x >> 5, lane = threadIdx.x & 31;
    int n = blockIdx.x * 8 + warp;
    if (n >= PN) return;
    int tgt = targets[n];
    const float4* xr = (const float4*)(inputs + ((size_t)n << 10));
    const float4* wr = (const float4*)(kern + ((size_t)tgt << 10));
    float d = 0.f;
#pragma unroll
    for (int it = 0; it < 8; ++it) {
        float4 a = xr[lane + it * 32];
        float4 b = wr[lane + it * 32];
        d += a.x * b.x + a.y * b.y + a.z * b.z + a.w * b.w;
    }
#pragma unroll
    for (int o = 16; o; o >>= 1) d += __shfl_down_sync(0xffffffffu, d, o);
    if (lane == 0) {
        g_true[n] = d + bias[tgt] + neg_log_expected(tgt);
        g_rowsum[n] = 0.f;
    }
}

// ---------------- fused GEMM (bf16 mma.sync) + exp epilogue ----------------
// CTA tile 128x128, 4 warps in 2(M) x 2(N), warp tile 64x64.
// K-chunk 64, 3-stage cp.async pipeline, register fragment double-buffering,
// cp.async issued in 4 quarters interleaved between MMA groups (de-bursted).
#define SLD 72                         // smem K stride (64 + 8 pad) in bf16
#define A_STG (128 * SLD * 2)          // 18432 B per operand stage
#define NSTG 3
#define OFF_B    (NSTG * A_STG)        // 55296
#define OFF_SROW (2 * NSTG * A_STG)    // 110592
#define SMEM_BYTES (OFF_SROW + 512)
#define NK (PC / 64)                   // 16 K-chunks

__global__ __launch_bounds__(128, 2) void gemm_exp_kernel(
    const int* __restrict__ targets, const int* __restrict__ sampled) {
    extern __shared__ char smem[];
    float* srow = (float*)(smem + OFF_SROW);

    const int tid = threadIdx.x;
    const int lane = tid & 31, warp = tid >> 5;
    const int wm = warp >> 1, wn = warp & 1;       // 2 x 2 warp grid
    const int bm = blockIdx.y * 128, bn = blockIdx.x * 128;

    float acc[4][8][4];
#pragma unroll
    for (int mi = 0; mi < 4; mi++)
#pragma unroll
        for (int ni = 0; ni < 8; ni++)
#pragma unroll
            for (int e = 0; e < 4; e++) acc[mi][ni][e] = 0.f;

    srow[tid] = 0.f;

    uint32_t sbase;
    asm("{ .reg .u64 t; cvta.to.shared.u64 t, %1; cvt.u32.u64 %0, t; }"
        : "=r"(sbase) : "l"(smem));
    const uint32_t sA = sbase;
    const uint32_t sB = sbase + OFF_B;

    // ldmatrix per-lane address components (within tile)
    const int arow  = wm * 64 + (lane & 7) + 8 * ((lane >> 3) & 1);
    const int acoff = (lane >> 4) * 8;
    const int brow  = wn * 64 + (lane & 7) + 8 * (lane >> 4);
    const int bcoff = ((lane >> 3) & 1) * 8;

    // global->shared: 1024 16B chunks per operand per stage, 8 per thread
    const int r0 = tid >> 3, c0 = tid & 7;   // rows r0 + it*16, it=0..7
    const __nv_bfloat16* Ag = g_X + (size_t)(bm + r0) * PC + c0 * 8;
    const __nv_bfloat16* Bg = g_W + (size_t)(bn + r0) * PC + c0 * 8;
    const uint32_t dA = sA + (uint32_t)(r0 * SLD + c0 * 8) * 2;
    const uint32_t dB = sB + (uint32_t)(r0 * SLD + c0 * 8) * 2;

// one quarter: rows it = 2q, 2q+1 for both operands (4 cp.async / thread)
#define LOAD_Q(kt_, so_, q_)                                                   \
    do {                                                                       \
        if ((kt_) < NK) {                                                      \
            uint32_t so = (uint32_t)(so_) * A_STG;                             \
            int ko = (kt_) * 64;                                               \
            CP_ASYNC16(dA + so + (uint32_t)(((q_) * 2) * 16 * SLD * 2),        \
                       Ag + ko + (size_t)((q_) * 2) * 16 * PC);                \
            CP_ASYNC16(dA + so + (uint32_t)(((q_) * 2 + 1) * 16 * SLD * 2),    \
                       Ag + ko + (size_t)((q_) * 2 + 1) * 16 * PC);            \
            CP_ASYNC16(dB + so + (uint32_t)(((q_) * 2) * 16 * SLD * 2),        \
                       Bg + ko + (size_t)((q_) * 2) * 16 * PC);                \
            CP_ASYNC16(dB + so + (uint32_t)(((q_) * 2 + 1) * 16 * SLD * 2),    \
                       Bg + ko + (size_t)((q_) * 2 + 1) * 16 * PC);            \
        }                                                                      \
    } while (0)

#define LOAD_STAGE(kt_, so_)                                                   \
    do {                                                                       \
        LOAD_Q(kt_, so_, 0); LOAD_Q(kt_, so_, 1);                              \
        LOAD_Q(kt_, so_, 2); LOAD_Q(kt_, so_, 3);                              \
        asm volatile("cp.async.commit_group;" ::: "memory");                   \
    } while (0)

    uint32_t afr[2][4][4];
    uint32_t bfr[2][8][2];

#define LDFRAG(buf_, ca_, cb_, ks_)                                            \
    do {                                                                       \
        _Pragma("unroll")                                                      \
        for (int mi = 0; mi < 4; mi++)                                         \
            ldm_x4(afr[buf_][mi], (ca_) +                                      \
                (uint32_t)(((arow + mi * 16) * SLD + (ks_) * 16 + acoff) * 2));\
        _Pragma("unroll")                                                      \
        for (int nb = 0; nb < 4; nb++) {                                       \
            uint32_t r[4];                                                     \
            ldm_x4(r, (cb_) +                                                  \
                (uint32_t)(((brow + nb * 16) * SLD + (ks_) * 16 + bcoff) * 2));\
            bfr[buf_][2 * nb][0] = r[0];                                       \
            bfr[buf_][2 * nb][1] = r[1];                                       \
            bfr[buf_][2 * nb + 1][0] = r[2];                                   \
            bfr[buf_][2 * nb + 1][1] = r[3];                                   \
        }                                                                      \
    } while (0)

#define MMA_GROUP(buf_)                                                        \
    do {                                                                       \
        _Pragma("unroll")                                                      \
        for (int mi = 0; mi < 4; mi++)                                         \
            _Pragma("unroll")                                                  \
            for (int ni = 0; ni < 8; ni++)                                     \
                mma_bf16(acc[mi][ni], afr[buf_][mi], bfr[buf_][ni][0],         \
                         bfr[buf_][ni][1]);                                    \
    } while (0)

    // prologue: stages 0,1 in flight; stage 0 ready; preload ks=0 fragments
    LOAD_STAGE(0, 0);
    LOAD_STAGE(1, 1);
    asm volatile("cp.async.wait_group 1;" ::: "memory");
    __syncthreads();

    int s_cur = 0, s_ld = 2;
    uint32_t ca = sA, cb = sB;
    LDFRAG(0, ca, cb, 0);

#pragma unroll 1
    for (int kt = 0; kt < NK; ++kt) {
        // loads for stage kt+2 into buffer s_ld (== stage kt-1, consumed);
        // issued in quarters between MMA groups to avoid LSU issue bursts.
        LOAD_Q(kt + 2, s_ld, 0);
        LDFRAG(1, ca, cb, 1);
        MMA_GROUP(0);

        LOAD_Q(kt + 2, s_ld, 1);
        LDFRAG(0, ca, cb, 2);
        MMA_GROUP(1);

        LOAD_Q(kt + 2, s_ld, 2);
        LDFRAG(1, ca, cb, 3);
        MMA_GROUP(0);

        LOAD_Q(kt + 2, s_ld, 3);
        asm volatile("cp.async.commit_group;" ::: "memory");
        MMA_GROUP(1);

        s_ld = (s_ld == 2) ? 0 : s_ld + 1;

        if (kt + 1 < NK) {
            asm volatile("cp.async.wait_group 1;" ::: "memory");
            __syncthreads();
            s_cur = (s_cur == 2) ? 0 : s_cur + 1;
            ca = sA + (uint32_t)s_cur * A_STG;
            cb = sB + (uint32_t)s_cur * A_STG;
            LDFRAG(0, ca, cb, 0);
        }
    }

    // ---- epilogue: corrected logits -> exp -> per-row partial sums ----
    int tg[4][2];
#pragma unroll
    for (int mi = 0; mi < 4; mi++)
#pragma unroll
        for (int h = 0; h < 2; h++)
            tg[mi][h] = targets[bm + wm * 64 + mi * 16 + (lane >> 2) + h * 8];

    float rs[4][2];
#pragma unroll
    for (int mi = 0; mi < 4; mi++) { rs[mi][0] = 0.f; rs[mi][1] = 0.f; }

#pragma unroll
    for (int ni = 0; ni < 8; ni++) {
#pragma unroll
        for (int j = 0; j < 2; j++) {
            int col = bn + wn * 64 + ni * 8 + ((lane & 3) << 1) + j;
            int sid = sampled[col];
            float bc = g_bcorr[col];
#pragma unroll
            for (int mi = 0; mi < 4; mi++) {
#pragma unroll
                for (int h = 0; h < 2; h++) {
                    if (sid != tg[mi][h])
                        rs[mi][h] += __expf(acc[mi][ni][h * 2 + j] + bc);
                }
            }
        }
    }

#pragma unroll
    for (int mi = 0; mi < 4; mi++) {
#pragma unroll
        for (int h = 0; h < 2; h++) {
            float v = rs[mi][h];
            v += __shfl_xor_sync(0xffffffffu, v, 1);
            v += __shfl_xor_sync(0xffffffffu, v, 2);
            if ((lane & 3) == 0)
                atomicAdd(&srow[wm * 64 + mi * 16 + (lane >> 2) + h * 8], v);
        }
    }
    __syncthreads();
    atomicAdd(&g_rowsum[bm + tid], srow[tid]);
}

// ---------------- finalize: per-example loss + mean ----------------
__global__ void finalize_kernel(float* __restrict__ out) {
    __shared__ double sh[32];
    double local = 0.0;
    for (int n = threadIdx.x; n < PN; n += 1024) {
        float t = g_true[n];
        float v = logf(g_rowsum[n] + expf(t)) - t;
        local += (double)v;
    }
#pragma unroll
    for (int o = 16; o; o >>= 1) local += __shfl_down_sync(0xffffffffu, local, o);
    if ((threadIdx.x & 31) == 0) sh[threadIdx.x >> 5] = local;
    __syncthreads();
    if (threadIdx.x < 32) {
        double v = sh[threadIdx.x];
#pragma unroll
        for (int o = 16; o; o >>= 1) v += __shfl_down_sync(0xffffffffu, v, o);
        if (threadIdx.x == 0) out[0] = (float)(v / (double)PN);
    }
}

// ---------------- entry ----------------
extern "C" void kernel_launch(void* const* d_in, const int* in_sizes, int n_in,
                              void* d_out, int out_size) {
    const float* inputs  = (const float*)d_in[0];
    const int*   targets = (const int*)d_in[1];
    const int*   sampled = (const int*)d_in[2];
    const float* kern    = (const float*)d_in[3];
    const float* bias    = (const float*)d_in[4];
    float* out = (float*)d_out;

    static int smem_set = 0;
    if (!smem_set) {
        cudaFuncSetAttribute(gemm_exp_kernel,
                             cudaFuncAttributeMaxDynamicSharedMemorySize, SMEM_BYTES);
        smem_set = 1;
    }

    prep_gather_kernel<<<4096, 256>>>(inputs, sampled, kern, bias);
    prep_true_kernel<<<PN / 8, 256>>>(inputs, targets, kern, bias);

    dim3 grid(PS / 128, PN / 128);
    gemm_exp_kernel<<<grid, 128, SMEM_BYTES>>>(targets, sampled);

    finalize_kernel<<<1, 1024>>>(out);
}

// round 13
// speedup vs baseline: 1.1103x; 1.0174x over previous
#include <cuda_runtime.h>
#include <cuda_bf16.h>
#include <cstdint>

// Problem constants
#define PN 8192      // batch rows
#define PC 1024      // feature dim
#define PS 8192      // negatives (sampled)
#define PUNITS 128000

// ---------------- device scratch (static, allocation-free) ----------------
__device__ __nv_bfloat16 g_X[PN * PC];   // inputs in bf16           (16 MB)
__device__ __nv_bfloat16 g_W[PS * PC];   // gathered sampled rows    (16 MB)
__device__ float g_bcorr[PS];            // bias[sampled] - log(E(sampled))
__device__ float g_true[PN];             // corrected true logits
__device__ float g_rowsum[PN];           // sum_s exp(corrected samp logit)
__device__ double g_part[64];            // finalize block partials
__device__ unsigned int g_tick;          // finalize ticket counter

// ---------------- helpers ----------------
__device__ __forceinline__ float neg_log_expected(int id) {
    float idf = (float)id;
    float p = (logf(idf + 2.0f) - logf(idf + 1.0f)) / logf((float)(PUNITS + 1));
    float e = -expm1f((float)PS * log1pf(-p));
    return -logf(e);
}

__device__ __forceinline__ void ldm_x4(uint32_t (&r)[4], uint32_t saddr) {
    asm volatile("ldmatrix.sync.aligned.m8n8.x4.shared.b16 {%0,%1,%2,%3}, [%4];"
                 : "=r"(r[0]), "=r"(r[1]), "=r"(r[2]), "=r"(r[3])
                 : "r"(saddr));
}

__device__ __forceinline__ void mma_bf16(float (&c)[4], const uint32_t (&a)[4],
                                         const uint32_t b0, const uint32_t b1) {
    asm volatile(
        "mma.sync.aligned.m16n8k16.row.col.f32.bf16.bf16.f32 "
        "{%0,%1,%2,%3}, {%4,%5,%6,%7}, {%8,%9}, {%0,%1,%2,%3};"
        : "+f"(c[0]), "+f"(c[1]), "+f"(c[2]), "+f"(c[3])
        : "r"(a[0]), "r"(a[1]), "r"(a[2]), "r"(a[3]), "r"(b0), "r"(b1));
}

#define CP_ASYNC16(dst, src) \
    asm volatile("cp.async.cg.shared.global [%0], [%1], 16;" :: "r"(dst), "l"(src))

// ---------------- prep: convert + gather + bcorr + true logits (fused) -------
__global__ void prep_kernel(const float* __restrict__ inputs,
                            const int* __restrict__ sampled,
                            const int* __restrict__ targets,
                            const float* __restrict__ kern,
                            const float* __restrict__ bias) {
    const int gid = blockIdx.x * blockDim.x + threadIdx.x;
    if (gid == 0) g_tick = 0;
    if (gid < PS) {
        int sid = sampled[gid];
        g_bcorr[gid] = bias[sid] + neg_log_expected(sid);
    }
    const int total4 = (PN * PC) / 4;
    for (int i = gid; i < total4; i += gridDim.x * blockDim.x) {
        float4 x = ((const float4*)inputs)[i];
        __nv_bfloat162* dx = (__nv_bfloat162*)g_X + (size_t)i * 2;
        dx[0] = __floats2bfloat162_rn(x.x, x.y);
        dx[1] = __floats2bfloat162_rn(x.z, x.w);

        int s  = i >> 8;
        int c4 = i & 255;
        float4 w = ((const float4*)(kern + ((size_t)sampled[s] << 10)))[c4];
        __nv_bfloat162* dw = (__nv_bfloat162*)g_W + (size_t)i * 2;
        dw[0] = __floats2bfloat162_rn(w.x, w.y);
        dw[1] = __floats2bfloat162_rn(w.z, w.w);
    }

    // true logits: blocks 0..PN/8-1 also compute 8 rows each (one per warp)
    if (blockIdx.x < PN / 8) {
        int warp = threadIdx.x >> 5, lane = threadIdx.x & 31;
        int n = blockIdx.x * 8 + warp;
        int tgt = targets[n];
        const float4* xr = (const float4*)(inputs + ((size_t)n << 10));
        const float4* wr = (const float4*)(kern + ((size_t)tgt << 10));
        float d = 0.f;
#pragma unroll
        for (int it = 0; it < 8; ++it) {
            float4 a = xr[lane + it * 32];
            float4 b = wr[lane + it * 32];
            d += a.x * b.x + a.y * b.y + a.z * b.z + a.w * b.w;
        }
#pragma unroll
        for (int o = 16; o; o >>= 1) d += __shfl_down_sync(0xffffffffu, d, o);
        if (lane == 0) {
            g_true[n] = d + bias[tgt] + neg_log_expected(tgt);
            g_rowsum[n] = 0.f;
        }
    }
}

// ---------------- fused GEMM (bf16 mma.sync) + exp epilogue ----------------
// CTA tile 128x128, 4 warps in 2(M) x 2(N), warp tile 64x64.
// K-chunk 64, 3-stage cp.async pipeline, register fragment double-buffering,
// cp.async issued in 4 quarters interleaved between MMA groups (de-bursted).
#define SLD 72                         // smem K stride (64 + 8 pad) in bf16
#define A_STG (128 * SLD * 2)          // 18432 B per operand stage
#define NSTG 3
#define OFF_B    (NSTG * A_STG)        // 55296
#define OFF_SROW (2 * NSTG * A_STG)    // 110592
#define SMEM_BYTES (OFF_SROW + 512)
#define NK (PC / 64)                   // 16 K-chunks

__global__ __launch_bounds__(128, 2) void gemm_exp_kernel(
    const int* __restrict__ targets, const int* __restrict__ sampled) {
    extern __shared__ char smem[];
    float* srow = (float*)(smem + OFF_SROW);

    const int tid = threadIdx.x;
    const int lane = tid & 31, warp = tid >> 5;
    const int wm = warp >> 1, wn = warp & 1;       // 2 x 2 warp grid
    const int bm = blockIdx.y * 128, bn = blockIdx.x * 128;

    float acc[4][8][4];
#pragma unroll
    for (int mi = 0; mi < 4; mi++)
#pragma unroll
        for (int ni = 0; ni < 8; ni++)
#pragma unroll
            for (int e = 0; e < 4; e++) acc[mi][ni][e] = 0.f;

    srow[tid] = 0.f;

    uint32_t sbase;
    asm("{ .reg .u64 t; cvta.to.shared.u64 t, %1; cvt.u32.u64 %0, t; }"
        : "=r"(sbase) : "l"(smem));
    const uint32_t sA = sbase;
    const uint32_t sB = sbase + OFF_B;

    // ldmatrix per-lane address components (within tile)
    const int arow  = wm * 64 + (lane & 7) + 8 * ((lane >> 3) & 1);
    const int acoff = (lane >> 4) * 8;
    const int brow  = wn * 64 + (lane & 7) + 8 * (lane >> 4);
    const int bcoff = ((lane >> 3) & 1) * 8;

    // global->shared: 1024 16B chunks per operand per stage, 8 per thread
    const int r0 = tid >> 3, c0 = tid & 7;   // rows r0 + it*16, it=0..7
    const __nv_bfloat16* Ag = g_X + (size_t)(bm + r0) * PC + c0 * 8;
    const __nv_bfloat16* Bg = g_W + (size_t)(bn + r0) * PC + c0 * 8;
    const uint32_t dA = sA + (uint32_t)(r0 * SLD + c0 * 8) * 2;
    const uint32_t dB = sB + (uint32_t)(r0 * SLD + c0 * 8) * 2;

// one quarter: rows it = 2q, 2q+1 for both operands (4 cp.async / thread)
#define LOAD_Q(kt_, so_, q_)                                                   \
    do {                                                                       \
        if ((kt_) < NK) {                                                      \
            uint32_t so = (uint32_t)(so_) * A_STG;                             \
            int ko = (kt_) * 64;                                               \
            CP_ASYNC16(dA + so + (uint32_t)(((q_) * 2) * 16 * SLD * 2),        \
                       Ag + ko + (size_t)((q_) * 2) * 16 * PC);                \
            CP_ASYNC16(dA + so + (uint32_t)(((q_) * 2 + 1) * 16 * SLD * 2),    \
                       Ag + ko + (size_t)((q_) * 2 + 1) * 16 * PC);            \
            CP_ASYNC16(dB + so + (uint32_t)(((q_) * 2) * 16 * SLD * 2),        \
                       Bg + ko + (size_t)((q_) * 2) * 16 * PC);                \
            CP_ASYNC16(dB + so + (uint32_t)(((q_) * 2 + 1) * 16 * SLD * 2),    \
                       Bg + ko + (size_t)((q_) * 2 + 1) * 16 * PC);            \
        }                                                                      \
    } while (0)

#define LOAD_STAGE(kt_, so_)                                                   \
    do {                                                                       \
        LOAD_Q(kt_, so_, 0); LOAD_Q(kt_, so_, 1);                              \
        LOAD_Q(kt_, so_, 2); LOAD_Q(kt_, so_, 3);                              \
        asm volatile("cp.async.commit_group;" ::: "memory");                   \
    } while (0)

    uint32_t afr[2][4][4];
    uint32_t bfr[2][8][2];

#define LDFRAG(buf_, ca_, cb_, ks_)                                            \
    do {                                                                       \
        _Pragma("unroll")                                                      \
        for (int mi = 0; mi < 4; mi++)                                         \
            ldm_x4(afr[buf_][mi], (ca_) +                                      \
                (uint32_t)(((arow + mi * 16) * SLD + (ks_) * 16 + acoff) * 2));\
        _Pragma("unroll")                                                      \
        for (int nb = 0; nb < 4; nb++) {                                       \
            uint32_t r[4];                                                     \
            ldm_x4(r, (cb_) +                                                  \
                (uint32_t)(((brow + nb * 16) * SLD + (ks_) * 16 + bcoff) * 2));\
            bfr[buf_][2 * nb][0] = r[0];                                       \
            bfr[buf_][2 * nb][1] = r[1];                                       \
            bfr[buf_][2 * nb + 1][0] = r[2];                                   \
            bfr[buf_][2 * nb + 1][1] = r[3];                                   \
        }                                                                      \
    } while (0)

#define MMA_GROUP(buf_)                                                        \
    do {                                                                       \
        _Pragma("unroll")                                                      \
        for (int mi = 0; mi < 4; mi++)                                         \
            _Pragma("unroll")                                                  \
            for (int ni = 0; ni < 8; ni++)                                     \
                mma_bf16(acc[mi][ni], afr[buf_][mi], bfr[buf_][ni][0],         \
                         bfr[buf_][ni][1]);                                    \
    } while (0)

    // prologue: stages 0,1 in flight; stage 0 ready; preload ks=0 fragments
    LOAD_STAGE(0, 0);
    LOAD_STAGE(1, 1);
    asm volatile("cp.async.wait_group 1;" ::: "memory");
    __syncthreads();

    int s_cur = 0, s_ld = 2;
    uint32_t ca = sA, cb = sB;
    LDFRAG(0, ca, cb, 0);

#pragma unroll 1
    for (int kt = 0; kt < NK; ++kt) {
        // loads for stage kt+2 into buffer s_ld (== stage kt-1, consumed);
        // issued in quarters between MMA groups to avoid LSU issue bursts.
        LOAD_Q(kt + 2, s_ld, 0);
        LDFRAG(1, ca, cb, 1);
        MMA_GROUP(0);

        LOAD_Q(kt + 2, s_ld, 1);
        LDFRAG(0, ca, cb, 2);
        MMA_GROUP(1);

        LOAD_Q(kt + 2, s_ld, 2);
        LDFRAG(1, ca, cb, 3);
        MMA_GROUP(0);

        LOAD_Q(kt + 2, s_ld, 3);
        asm volatile("cp.async.commit_group;" ::: "memory");
        MMA_GROUP(1);

        s_ld = (s_ld == 2) ? 0 : s_ld + 1;

        if (kt + 1 < NK) {
            asm volatile("cp.async.wait_group 1;" ::: "memory");
            __syncthreads();
            s_cur = (s_cur == 2) ? 0 : s_cur + 1;
            ca = sA + (uint32_t)s_cur * A_STG;
            cb = sB + (uint32_t)s_cur * A_STG;
            LDFRAG(0, ca, cb, 0);
        }
    }

    // ---- epilogue: corrected logits -> exp -> per-row partial sums ----
    int tg[4][2];
#pragma unroll
    for (int mi = 0; mi < 4; mi++)
#pragma unroll
        for (int h = 0; h < 2; h++)
            tg[mi][h] = targets[bm + wm * 64 + mi * 16 + (lane >> 2) + h * 8];

    float rs[4][2];
#pragma unroll
    for (int mi = 0; mi < 4; mi++) { rs[mi][0] = 0.f; rs[mi][1] = 0.f; }

#pragma unroll
    for (int ni = 0; ni < 8; ni++) {
#pragma unroll
        for (int j = 0; j < 2; j++) {
            int col = bn + wn * 64 + ni * 8 + ((lane & 3) << 1) + j;
            int sid = sampled[col];
            float bc = g_bcorr[col];
#pragma unroll
            for (int mi = 0; mi < 4; mi++) {
#pragma unroll
                for (int h = 0; h < 2; h++) {
                    if (sid != tg[mi][h])
                        rs[mi][h] += __expf(acc[mi][ni][h * 2 + j] + bc);
                }
            }
        }
    }

#pragma unroll
    for (int mi = 0; mi < 4; mi++) {
#pragma unroll
        for (int h = 0; h < 2; h++) {
            float v = rs[mi][h];
            v += __shfl_xor_sync(0xffffffffu, v, 1);
            v += __shfl_xor_sync(0xffffffffu, v, 2);
            if ((lane & 3) == 0)
                atomicAdd(&srow[wm * 64 + mi * 16 + (lane >> 2) + h * 8], v);
        }
    }
    __syncthreads();
    atomicAdd(&g_rowsum[bm + tid], srow[tid]);
}

// ---------------- finalize: parallel per-example loss + mean ----------------
// 64 blocks x 128 threads, one row per thread; last block (ticket) reduces
// the 64 deterministic block partials and writes the mean.
__global__ void finalize_kernel(float* __restrict__ out) {
    __shared__ double sh[4];
    const int n = blockIdx.x * 128 + threadIdx.x;
    const int lane = threadIdx.x & 31, wid = threadIdx.x >> 5;

    float t = g_true[n];
    double local = (double)(logf(g_rowsum[n] + expf(t)) - t);
#pragma unroll
    for (int o = 16; o; o >>= 1) local += __shfl_down_sync(0xffffffffu, local, o);
    if (lane == 0) sh[wid] = local;
    __syncthreads();
    if (threadIdx.x == 0) {
        double s = sh[0] + sh[1] + sh[2] + sh[3];
        g_part[blockIdx.x] = s;
        __threadfence();
        unsigned int r = atomicAdd(&g_tick, 1u);
        if (r == 63u) {
            double tot = 0.0;
#pragma unroll 8
            for (int i = 0; i < 64; ++i) tot += g_part[i];
            out[0] = (float)(tot / (double)PN);
        }
    }
}

// ---------------- entry ----------------
extern "C" void kernel_launch(void* const* d_in, const int* in_sizes, int n_in,
                              void* d_out, int out_size) {
    const float* inputs  = (const float*)d_in[0];
    const int*   targets = (const int*)d_in[1];
    const int*   sampled = (const int*)d_in[2];
    const float* kern    = (const float*)d_in[3];
    const float* bias    = (const float*)d_in[4];
    float* out = (float*)d_out;

    static int smem_set = 0;
    if (!smem_set) {
        cudaFuncSetAttribute(gemm_exp_kernel,
                             cudaFuncAttributeMaxDynamicSharedMemorySize, SMEM_BYTES);
        smem_set = 1;
    }

    prep_kernel<<<4096, 256>>>(inputs, sampled, targets, kern, bias);

    dim3 grid(PS / 128, PN / 128);
    gemm_exp_kernel<<<grid, 128, SMEM_BYTES>>>(targets, sampled);

    finalize_kernel<<<64, 128>>>(out);
}

// round 14
// speedup vs baseline: 1.1118x; 1.0014x over previous
#include <cuda_runtime.h>
#include <cuda_bf16.h>
#include <cstdint>

// Problem constants
#define PN 8192      // batch rows
#define PC 1024      // feature dim
#define PS 8192      // negatives (sampled)
#define PUNITS 128000

// ---------------- device scratch (static, allocation-free) ----------------
__device__ __nv_bfloat16 g_X[PN * PC];   // inputs in bf16           (16 MB)
__device__ __nv_bfloat16 g_W[PS * PC];   // gathered sampled rows    (16 MB)
__device__ float g_bcorr[PS];            // bias[sampled] - log(E(sampled))
__device__ float g_true[PN];             // corrected true logits
__device__ float g_rowsum[PN];           // sum_s exp(corrected samp logit)
__device__ double g_part[64];            // finalize block partials
__device__ unsigned int g_tick;          // finalize ticket counter

// ---------------- helpers ----------------
__device__ __forceinline__ float neg_log_expected(int id) {
    float idf = (float)id;
    float p = (logf(idf + 2.0f) - logf(idf + 1.0f)) / logf((float)(PUNITS + 1));
    float e = -expm1f((float)PS * log1pf(-p));
    return -logf(e);
}

__device__ __forceinline__ uint32_t pack_bf2(float a, float b) {
    __nv_bfloat162 v = __floats2bfloat162_rn(a, b);
    uint32_t u;
    memcpy(&u, &v, 4);
    return u;
}

__device__ __forceinline__ uint4 pack8(const float4 v0, const float4 v1) {
    uint4 r;
    r.x = pack_bf2(v0.x, v0.y);
    r.y = pack_bf2(v0.z, v0.w);
    r.z = pack_bf2(v1.x, v1.y);
    r.w = pack_bf2(v1.z, v1.w);
    return r;
}

__device__ __forceinline__ void ldm_x4(uint32_t (&r)[4], uint32_t saddr) {
    asm volatile("ldmatrix.sync.aligned.m8n8.x4.shared.b16 {%0,%1,%2,%3}, [%4];"
                 : "=r"(r[0]), "=r"(r[1]), "=r"(r[2]), "=r"(r[3])
                 : "r"(saddr));
}

__device__ __forceinline__ void mma_bf16(float (&c)[4], const uint32_t (&a)[4],
                                         const uint32_t b0, const uint32_t b1) {
    asm volatile(
        "mma.sync.aligned.m16n8k16.row.col.f32.bf16.bf16.f32 "
        "{%0,%1,%2,%3}, {%4,%5,%6,%7}, {%8,%9}, {%0,%1,%2,%3};"
        : "+f"(c[0]), "+f"(c[1]), "+f"(c[2]), "+f"(c[3])
        : "r"(a[0]), "r"(a[1]), "r"(a[2]), "r"(a[3]), "r"(b0), "r"(b1));
}

#define CP_ASYNC16(dst, src) \
    asm volatile("cp.async.cg.shared.global [%0], [%1], 16;" :: "r"(dst), "l"(src))

// ---------------- prep: convert + gather + bcorr + true logits (fused) -------
// 4096 blocks x 256 threads = 1M threads; each handles exactly 8 floats of X
// and 8 floats of gathered W (two float4 loads each, one uint4 store each).
__global__ void prep_kernel(const float* __restrict__ inputs,
                            const int* __restrict__ sampled,
                            const int* __restrict__ targets,
                            const float* __restrict__ kern,
                            const float* __restrict__ bias) {
    const int gid = blockIdx.x * blockDim.x + threadIdx.x;
    if (gid == 0) g_tick = 0;
    if (gid < PS) {
        int sid = sampled[gid];
        g_bcorr[gid] = bias[sid] + neg_log_expected(sid);
    }

    // X: 8 floats at offset 8*gid
    const float4* xp = (const float4*)inputs + 2 * gid;
    float4 x0 = xp[0];
    float4 x1 = xp[1];
    // W: row s = (8*gid)/1024, 8 floats within the gathered source row
    const int s  = gid >> 7;        // 8*gid / 1024
    const int c8 = gid & 127;       // 8-float chunk within row
    const float4* wp = (const float4*)(kern + ((size_t)sampled[s] << 10)) + 2 * c8;
    float4 w0 = wp[0];
    float4 w1 = wp[1];

    ((uint4*)g_X)[gid] = pack8(x0, x1);
    ((uint4*)g_W)[gid] = pack8(w0, w1);

    // true logits: blocks 0..PN/8-1 compute 8 rows each (one per warp)
    if (blockIdx.x < PN / 8) {
        int warp = threadIdx.x >> 5, lane = threadIdx.x & 31;
        int n = blockIdx.x * 8 + warp;
        int tgt = targets[n];
        const float4* xr = (const float4*)(inputs + ((size_t)n << 10));
        const float4* wr = (const float4*)(kern + ((size_t)tgt << 10));
        float d = 0.f;
#pragma unroll
        for (int it = 0; it < 8; ++it) {
            float4 a = xr[lane + it * 32];
            float4 b = wr[lane + it * 32];
            d += a.x * b.x + a.y * b.y + a.z * b.z + a.w * b.w;
        }
#pragma unroll
        for (int o = 16; o; o >>= 1) d += __shfl_down_sync(0xffffffffu, d, o);
        if (lane == 0) {
            g_true[n] = d + bias[tgt] + neg_log_expected(tgt);
            g_rowsum[n] = 0.f;
        }
    }
}

// ---------------- fused GEMM (bf16 mma.sync) + exp epilogue ----------------
// CTA tile 128x128, 4 warps in 2(M) x 2(N), warp tile 64x64.
// K-chunk 64, 3-stage cp.async pipeline, register fragment double-buffering,
// cp.async issued in 4 quarters interleaved between MMA groups (de-bursted).
#define SLD 72                         // smem K stride (64 + 8 pad) in bf16
#define A_STG (128 * SLD * 2)          // 18432 B per operand stage
#define NSTG 3
#define OFF_B    (NSTG * A_STG)        // 55296
#define OFF_SROW (2 * NSTG * A_STG)    // 110592
#define SMEM_BYTES (OFF_SROW + 512)
#define NK (PC / 64)                   // 16 K-chunks

__global__ __launch_bounds__(128, 2) void gemm_exp_kernel(
    const int* __restrict__ targets, const int* __restrict__ sampled) {
    extern __shared__ char smem[];
    float* srow = (float*)(smem + OFF_SROW);

    const int tid = threadIdx.x;
    const int lane = tid & 31, warp = tid >> 5;
    const int wm = warp >> 1, wn = warp & 1;       // 2 x 2 warp grid
    const int bm = blockIdx.y * 128, bn = blockIdx.x * 128;

    float acc[4][8][4];
#pragma unroll
    for (int mi = 0; mi < 4; mi++)
#pragma unroll
        for (int ni = 0; ni < 8; ni++)
#pragma unroll
            for (int e = 0; e < 4; e++) acc[mi][ni][e] = 0.f;

    srow[tid] = 0.f;

    uint32_t sbase;
    asm("{ .reg .u64 t; cvta.to.shared.u64 t, %1; cvt.u32.u64 %0, t; }"
        : "=r"(sbase) : "l"(smem));
    const uint32_t sA = sbase;
    const uint32_t sB = sbase + OFF_B;

    // ldmatrix per-lane address components (within tile)
    const int arow  = wm * 64 + (lane & 7) + 8 * ((lane >> 3) & 1);
    const int acoff = (lane >> 4) * 8;
    const int brow  = wn * 64 + (lane & 7) + 8 * (lane >> 4);
    const int bcoff = ((lane >> 3) & 1) * 8;

    // global->shared: 1024 16B chunks per operand per stage, 8 per thread
    const int r0 = tid >> 3, c0 = tid & 7;   // rows r0 + it*16, it=0..7
    const __nv_bfloat16* Ag = g_X + (size_t)(bm + r0) * PC + c0 * 8;
    const __nv_bfloat16* Bg = g_W + (size_t)(bn + r0) * PC + c0 * 8;
    const uint32_t dA = sA + (uint32_t)(r0 * SLD + c0 * 8) * 2;
    const uint32_t dB = sB + (uint32_t)(r0 * SLD + c0 * 8) * 2;

// one quarter: rows it = 2q, 2q+1 for both operands (4 cp.async / thread)
#define LOAD_Q(kt_, so_, q_)                                                   \
    do {                                                                       \
        if ((kt_) < NK) {                                                      \
            uint32_t so = (uint32_t)(so_) * A_STG;                             \
            int ko = (kt_) * 64;                                               \
            CP_ASYNC16(dA + so + (uint32_t)(((q_) * 2) * 16 * SLD * 2),        \
                       Ag + ko + (size_t)((q_) * 2) * 16 * PC);                \
            CP_ASYNC16(dA + so + (uint32_t)(((q_) * 2 + 1) * 16 * SLD * 2),    \
                       Ag + ko + (size_t)((q_) * 2 + 1) * 16 * PC);            \
            CP_ASYNC16(dB + so + (uint32_t)(((q_) * 2) * 16 * SLD * 2),        \
                       Bg + ko + (size_t)((q_) * 2) * 16 * PC);                \
            CP_ASYNC16(dB + so + (uint32_t)(((q_) * 2 + 1) * 16 * SLD * 2),    \
                       Bg + ko + (size_t)((q_) * 2 + 1) * 16 * PC);            \
        }                                                                      \
    } while (0)

#define LOAD_STAGE(kt_, so_)                                                   \
    do {                                                                       \
        LOAD_Q(kt_, so_, 0); LOAD_Q(kt_, so_, 1);                              \
        LOAD_Q(kt_, so_, 2); LOAD_Q(kt_, so_, 3);                              \
        asm volatile("cp.async.commit_group;" ::: "memory");                   \
    } while (0)

    uint32_t afr[2][4][4];
    uint32_t bfr[2][8][2];

#define LDFRAG(buf_, ca_, cb_, ks_)                                            \
    do {                                                                       \
        _Pragma("unroll")                                                      \
        for (int mi = 0; mi < 4; mi++)                                         \
            ldm_x4(afr[buf_][mi], (ca_) +                                      \
                (uint32_t)(((arow + mi * 16) * SLD + (ks_) * 16 + acoff) * 2));\
        _Pragma("unroll")                                                      \
        for (int nb = 0; nb < 4; nb++) {                                       \
            uint32_t r[4];                                                     \
            ldm_x4(r, (cb_) +                                                  \
                (uint32_t)(((brow + nb * 16) * SLD + (ks_) * 16 + bcoff) * 2));\
            bfr[buf_][2 * nb][0] = r[0];                                       \
            bfr[buf_][2 * nb][1] = r[1];                                       \
            bfr[buf_][2 * nb + 1][0] = r[2];                                   \
            bfr[buf_][2 * nb + 1][1] = r[3];                                   \
        }                                                                      \
    } while (0)

#define MMA_GROUP(buf_)                                                        \
    do {                                                                       \
        _Pragma("unroll")                                                      \
        for (int mi = 0; mi < 4; mi++)                                         \
            _Pragma("unroll")                                                  \
            for (int ni = 0; ni < 8; ni++)                                     \
                mma_bf16(acc[mi][ni], afr[buf_][mi], bfr[buf_][ni][0],         \
                         bfr[buf_][ni][1]);                                    \
    } while (0)

    // prologue: stages 0,1 in flight; stage 0 ready; preload ks=0 fragments
    LOAD_STAGE(0, 0);
    LOAD_STAGE(1, 1);
    asm volatile("cp.async.wait_group 1;" ::: "memory");
    __syncthreads();

    int s_cur = 0, s_ld = 2;
    uint32_t ca = sA, cb = sB;
    LDFRAG(0, ca, cb, 0);

#pragma unroll 1
    for (int kt = 0; kt < NK; ++kt) {
        // loads for stage kt+2 into buffer s_ld (== stage kt-1, consumed);
        // issued in quarters between MMA groups to avoid LSU issue bursts.
        LOAD_Q(kt + 2, s_ld, 0);
        LDFRAG(1, ca, cb, 1);
        MMA_GROUP(0);

        LOAD_Q(kt + 2, s_ld, 1);
        LDFRAG(0, ca, cb, 2);
        MMA_GROUP(1);

        LOAD_Q(kt + 2, s_ld, 2);
        LDFRAG(1, ca, cb, 3);
        MMA_GROUP(0);

        LOAD_Q(kt + 2, s_ld, 3);
        asm volatile("cp.async.commit_group;" ::: "memory");
        MMA_GROUP(1);

        s_ld = (s_ld == 2) ? 0 : s_ld + 1;

        if (kt + 1 < NK) {
            asm volatile("cp.async.wait_group 1;" ::: "memory");
            __syncthreads();
            s_cur = (s_cur == 2) ? 0 : s_cur + 1;
            ca = sA + (uint32_t)s_cur * A_STG;
            cb = sB + (uint32_t)s_cur * A_STG;
            LDFRAG(0, ca, cb, 0);
        }
    }

    // ---- epilogue: corrected logits -> exp -> per-row partial sums ----
    int tg[4][2];
#pragma unroll
    for (int mi = 0; mi < 4; mi++)
#pragma unroll
        for (int h = 0; h < 2; h++)
            tg[mi][h] = targets[bm + wm * 64 + mi * 16 + (lane >> 2) + h * 8];

    float rs[4][2];
#pragma unroll
    for (int mi = 0; mi < 4; mi++) { rs[mi][0] = 0.f; rs[mi][1] = 0.f; }

#pragma unroll
    for (int ni = 0; ni < 8; ni++) {
#pragma unroll
        for (int j = 0; j < 2; j++) {
            int col = bn + wn * 64 + ni * 8 + ((lane & 3) << 1) + j;
            int sid = sampled[col];
            float bc = g_bcorr[col];
#pragma unroll
            for (int mi = 0; mi < 4; mi++) {
#pragma unroll
                for (int h = 0; h < 2; h++) {
                    if (sid != tg[mi][h])
                        rs[mi][h] += __expf(acc[mi][ni][h * 2 + j] + bc);
                }
            }
        }
    }

#pragma unroll
    for (int mi = 0; mi < 4; mi++) {
#pragma unroll
        for (int h = 0; h < 2; h++) {
            float v = rs[mi][h];
            v += __shfl_xor_sync(0xffffffffu, v, 1);
            v += __shfl_xor_sync(0xffffffffu, v, 2);
            if ((lane & 3) == 0)
                atomicAdd(&srow[wm * 64 + mi * 16 + (lane >> 2) + h * 8], v);
        }
    }
    __syncthreads();
    atomicAdd(&g_rowsum[bm + tid], srow[tid]);
}

// ---------------- finalize: parallel per-example loss + mean ----------------
__global__ void finalize_kernel(float* __restrict__ out) {
    __shared__ double sh[4];
    const int n = blockIdx.x * 128 + threadIdx.x;
    const int lane = threadIdx.x & 31, wid = threadIdx.x >> 5;

    float t = g_true[n];
    double local = (double)(logf(g_rowsum[n] + expf(t)) - t);
#pragma unroll
    for (int o = 16; o; o >>= 1) local += __shfl_down_sync(0xffffffffu, local, o);
    if (lane == 0) sh[wid] = local;
    __syncthreads();
    if (threadIdx.x == 0) {
        double s = sh[0] + sh[1] + sh[2] + sh[3];
        g_part[blockIdx.x] = s;
        __threadfence();
        unsigned int r = atomicAdd(&g_tick, 1u);
        if (r == 63u) {
            double tot = 0.0;
#pragma unroll 8
            for (int i = 0; i < 64; ++i) tot += g_part[i];
            out[0] = (float)(tot / (double)PN);
        }
    }
}

// ---------------- entry ----------------
extern "C" void kernel_launch(void* const* d_in, const int* in_sizes, int n_in,
                              void* d_out, int out_size) {
    const float* inputs  = (const float*)d_in[0];
    const int*   targets = (const int*)d_in[1];
    const int*   sampled = (const int*)d_in[2];
    const float* kern    = (const float*)d_in[3];
    const float* bias    = (const float*)d_in[4];
    float* out = (float*)d_out;

    static int smem_set = 0;
    if (!smem_set) {
        cudaFuncSetAttribute(gemm_exp_kernel,
                             cudaFuncAttributeMaxDynamicSharedMemorySize, SMEM_BYTES);
        smem_set = 1;
    }

    prep_kernel<<<4096, 256>>>(inputs, sampled, targets, kern, bias);

    dim3 grid(PS / 128, PN / 128);
    gemm_exp_kernel<<<grid, 128, SMEM_BYTES>>>(targets, sampled);

    finalize_kernel<<<64, 128>>>(out);
}

// round 15
// speedup vs baseline: 1.1119x; 1.0001x over previous
#include <cuda_runtime.h>
#include <cuda_bf16.h>
#include <cstdint>

// Problem constants
#define PN 8192      // batch rows
#define PC 1024      // feature dim
#define PS 8192      // negatives (sampled)
#define PUNITS 128000

// ---------------- device scratch (static, allocation-free) ----------------
__device__ __nv_bfloat16 g_X[PN * PC];   // inputs in bf16           (16 MB)
__device__ __nv_bfloat16 g_W[PS * PC];   // gathered sampled rows    (16 MB)
__device__ float g_bcorr[PS];            // bias[sampled] - log(E(sampled))
__device__ float g_true[PN];             // corrected true logits
__device__ float g_rowsum[PN];           // sum_s exp(corrected samp logit)
__device__ double g_part[64];            // finalize block partials
__device__ unsigned int g_tick;          // finalize ticket counter

// ---------------- helpers ----------------
__device__ __forceinline__ float neg_log_expected(int id) {
    float idf = (float)id;
    float p = (logf(idf + 2.0f) - logf(idf + 1.0f)) / logf((float)(PUNITS + 1));
    float e = -expm1f((float)PS * log1pf(-p));
    return -logf(e);
}

__device__ __forceinline__ uint32_t pack_bf2(float a, float b) {
    __nv_bfloat162 v = __floats2bfloat162_rn(a, b);
    uint32_t u;
    memcpy(&u, &v, 4);
    return u;
}

__device__ __forceinline__ uint4 pack8(const float4 v0, const float4 v1) {
    uint4 r;
    r.x = pack_bf2(v0.x, v0.y);
    r.y = pack_bf2(v0.z, v0.w);
    r.z = pack_bf2(v1.x, v1.y);
    r.w = pack_bf2(v1.z, v1.w);
    return r;
}

__device__ __forceinline__ void ldm_x4(uint32_t (&r)[4], uint32_t saddr) {
    asm volatile("ldmatrix.sync.aligned.m8n8.x4.shared.b16 {%0,%1,%2,%3}, [%4];"
                 : "=r"(r[0]), "=r"(r[1]), "=r"(r[2]), "=r"(r[3])
                 : "r"(saddr));
}

__device__ __forceinline__ void mma_bf16(float (&c)[4], const uint32_t (&a)[4],
                                         const uint32_t b0, const uint32_t b1) {
    asm volatile(
        "mma.sync.aligned.m16n8k16.row.col.f32.bf16.bf16.f32 "
        "{%0,%1,%2,%3}, {%4,%5,%6,%7}, {%8,%9}, {%0,%1,%2,%3};"
        : "+f"(c[0]), "+f"(c[1]), "+f"(c[2]), "+f"(c[3])
        : "r"(a[0]), "r"(a[1]), "r"(a[2]), "r"(a[3]), "r"(b0), "r"(b1));
}

#define CP_ASYNC16(dst, src) \
    asm volatile("cp.async.cg.shared.global [%0], [%1], 16;" :: "r"(dst), "l"(src))

// ---------------- prep: convert + gather + bcorr + true logits (fused) -------
// 2048 blocks x 256 threads; each thread handles TWO distant 8-float chunks
// of X and of gathered W (two independent gather chains -> MLP ~8-10).
#define HALF4 ((PN * PC) / 8 / 2)      // 524288: chunk count per half

__global__ void prep_kernel(const float* __restrict__ inputs,
                            const int* __restrict__ sampled,
                            const int* __restrict__ targets,
                            const float* __restrict__ kern,
                            const float* __restrict__ bias) {
    const int gid = blockIdx.x * blockDim.x + threadIdx.x;
    if (gid == 0) g_tick = 0;

    const int i0 = gid;
    const int i1 = gid + HALF4;

    // issue both sampled-id loads first (independent chains)
    const int s0 = i0 >> 7, s1 = i1 >> 7;
    const int sid0 = sampled[s0];
    const int sid1 = sampled[s1];

    // X loads (4 independent float4s)
    const float4* xp0 = (const float4*)inputs + 2 * i0;
    const float4* xp1 = (const float4*)inputs + 2 * i1;
    float4 x00 = xp0[0], x01 = xp0[1];
    float4 x10 = xp1[0], x11 = xp1[1];

    // W gather loads (4 independent float4s, addresses now resolved)
    const int c0 = i0 & 127, c1 = i1 & 127;
    const float4* wp0 = (const float4*)(kern + ((size_t)sid0 << 10)) + 2 * c0;
    const float4* wp1 = (const float4*)(kern + ((size_t)sid1 << 10)) + 2 * c1;
    float4 w00 = wp0[0], w01 = wp0[1];
    float4 w10 = wp1[0], w11 = wp1[1];

    ((uint4*)g_X)[i0] = pack8(x00, x01);
    ((uint4*)g_X)[i1] = pack8(x10, x11);
    ((uint4*)g_W)[i0] = pack8(w00, w01);
    ((uint4*)g_W)[i1] = pack8(w10, w11);

    if (gid < PS) {
        int sid = sampled[gid];
        g_bcorr[gid] = bias[sid] + neg_log_expected(sid);
    }

    // true logits: blocks 0..PN/8-1 compute 8 rows each (one per warp)
    if (blockIdx.x < PN / 8) {
        int warp = threadIdx.x >> 5, lane = threadIdx.x & 31;
        int n = blockIdx.x * 8 + warp;
        int tgt = targets[n];
        const float4* xr = (const float4*)(inputs + ((size_t)n << 10));
        const float4* wr = (const float4*)(kern + ((size_t)tgt << 10));
        float d = 0.f;
#pragma unroll
        for (int it = 0; it < 8; ++it) {
            float4 a = xr[lane + it * 32];
            float4 b = wr[lane + it * 32];
            d += a.x * b.x + a.y * b.y + a.z * b.z + a.w * b.w;
        }
#pragma unroll
        for (int o = 16; o; o >>= 1) d += __shfl_down_sync(0xffffffffu, d, o);
        if (lane == 0) {
            g_true[n] = d + bias[tgt] + neg_log_expected(tgt);
            g_rowsum[n] = 0.f;
        }
    }
}

// ---------------- fused GEMM (bf16 mma.sync) + exp epilogue ----------------
// CTA tile 128x128, 4 warps in 2(M) x 2(N), warp tile 64x64.
// K-chunk 64, 3-stage cp.async pipeline, register fragment double-buffering,
// cp.async issued in 4 quarters interleaved between MMA groups (de-bursted).
#define SLD 72                         // smem K stride (64 + 8 pad) in bf16
#define A_STG (128 * SLD * 2)          // 18432 B per operand stage
#define NSTG 3
#define OFF_B    (NSTG * A_STG)        // 55296
#define OFF_SROW (2 * NSTG * A_STG)    // 110592
#define SMEM_BYTES (OFF_SROW + 512)
#define NK (PC / 64)                   // 16 K-chunks

__global__ __launch_bounds__(128, 2) void gemm_exp_kernel(
    const int* __restrict__ targets, const int* __restrict__ sampled) {
    extern __shared__ char smem[];
    float* srow = (float*)(smem + OFF_SROW);

    const int tid = threadIdx.x;
    const int lane = tid & 31, warp = tid >> 5;
    const int wm = warp >> 1, wn = warp & 1;       // 2 x 2 warp grid
    const int bm = blockIdx.y * 128, bn = blockIdx.x * 128;

    float acc[4][8][4];
#pragma unroll
    for (int mi = 0; mi < 4; mi++)
#pragma unroll
        for (int ni = 0; ni < 8; ni++)
#pragma unroll
            for (int e = 0; e < 4; e++) acc[mi][ni][e] = 0.f;

    srow[tid] = 0.f;

    uint32_t sbase;
    asm("{ .reg .u64 t; cvta.to.shared.u64 t, %1; cvt.u32.u64 %0, t; }"
        : "=r"(sbase) : "l"(smem));
    const uint32_t sA = sbase;
    const uint32_t sB = sbase + OFF_B;

    // ldmatrix per-lane address components (within tile)
    const int arow  = wm * 64 + (lane & 7) + 8 * ((lane >> 3) & 1);
    const int acoff = (lane >> 4) * 8;
    const int brow  = wn * 64 + (lane & 7) + 8 * (lane >> 4);
    const int bcoff = ((lane >> 3) & 1) * 8;

    // global->shared: 1024 16B chunks per operand per stage, 8 per thread
    const int r0 = tid >> 3, c0 = tid & 7;   // rows r0 + it*16, it=0..7
    const __nv_bfloat16* Ag = g_X + (size_t)(bm + r0) * PC + c0 * 8;
    const __nv_bfloat16* Bg = g_W + (size_t)(bn + r0) * PC + c0 * 8;
    const uint32_t dA = sA + (uint32_t)(r0 * SLD + c0 * 8) * 2;
    const uint32_t dB = sB + (uint32_t)(r0 * SLD + c0 * 8) * 2;

// one quarter: rows it = 2q, 2q+1 for both operands (4 cp.async / thread)
#define LOAD_Q(kt_, so_, q_)                                                   \
    do {                                                                       \
        if ((kt_) < NK) {                                                      \
            uint32_t so = (uint32_t)(so_) * A_STG;                             \
            int ko = (kt_) * 64;                                               \
            CP_ASYNC16(dA + so + (uint32_t)(((q_) * 2) * 16 * SLD * 2),        \
                       Ag + ko + (size_t)((q_) * 2) * 16 * PC);                \
            CP_ASYNC16(dA + so + (uint32_t)(((q_) * 2 + 1) * 16 * SLD * 2),    \
                       Ag + ko + (size_t)((q_) * 2 + 1) * 16 * PC);            \
            CP_ASYNC16(dB + so + (uint32_t)(((q_) * 2) * 16 * SLD * 2),        \
                       Bg + ko + (size_t)((q_) * 2) * 16 * PC);                \
            CP_ASYNC16(dB + so + (uint32_t)(((q_) * 2 + 1) * 16 * SLD * 2),    \
                       Bg + ko + (size_t)((q_) * 2 + 1) * 16 * PC);            \
        }                                                                      \
    } while (0)

#define LOAD_STAGE(kt_, so_)                                                   \
    do {                                                                       \
        LOAD_Q(kt_, so_, 0); LOAD_Q(kt_, so_, 1);                              \
        LOAD_Q(kt_, so_, 2); LOAD_Q(kt_, so_, 3);                              \
        asm volatile("cp.async.commit_group;" ::: "memory");                   \
    } while (0)

    uint32_t afr[2][4][4];
    uint32_t bfr[2][8][2];

#define LDFRAG(buf_, ca_, cb_, ks_)                                            \
    do {                                                                       \
        _Pragma("unroll")                                                      \
        for (int mi = 0; mi < 4; mi++)                                         \
            ldm_x4(afr[buf_][mi], (ca_) +                                      \
                (uint32_t)(((arow + mi * 16) * SLD + (ks_) * 16 + acoff) * 2));\
        _Pragma("unroll")                                                      \
        for (int nb = 0; nb < 4; nb++) {                                       \
            uint32_t r[4];                                                     \
            ldm_x4(r, (cb_) +                                                  \
                (uint32_t)(((brow + nb * 16) * SLD + (ks_) * 16 + bcoff) * 2));\
            bfr[buf_][2 * nb][0] = r[0];                                       \
            bfr[buf_][2 * nb][1] = r[1];                                       \
            bfr[buf_][2 * nb + 1][0] = r[2];                                   \
            bfr[buf_][2 * nb + 1][1] = r[3];                                   \
        }                                                                      \
    } while (0)

#define MMA_GROUP(buf_)                                                        \
    do {                                                                       \
        _Pragma("unroll")                                                      \
        for (int mi = 0; mi < 4; mi++)                                         \
            _Pragma("unroll")                                                  \
            for (int ni = 0; ni < 8; ni++)                                     \
                mma_bf16(acc[mi][ni], afr[buf_][mi], bfr[buf_][ni][0],         \
                         bfr[buf_][ni][1]);                                    \
    } while (0)

    // prologue: stages 0,1 in flight; stage 0 ready; preload ks=0 fragments
    LOAD_STAGE(0, 0);
    LOAD_STAGE(1, 1);
    asm volatile("cp.async.wait_group 1;" ::: "memory");
    __syncthreads();

    int s_cur = 0, s_ld = 2;
    uint32_t ca = sA, cb = sB;
    LDFRAG(0, ca, cb, 0);

#pragma unroll 1
    for (int kt = 0; kt < NK; ++kt) {
        // loads for stage kt+2 into buffer s_ld (== stage kt-1, consumed);
        // issued in quarters between MMA groups to avoid LSU issue bursts.
        LOAD_Q(kt + 2, s_ld, 0);
        LDFRAG(1, ca, cb, 1);
        MMA_GROUP(0);

        LOAD_Q(kt + 2, s_ld, 1);
        LDFRAG(0, ca, cb, 2);
        MMA_GROUP(1);

        LOAD_Q(kt + 2, s_ld, 2);
        LDFRAG(1, ca, cb, 3);
        MMA_GROUP(0);

        LOAD_Q(kt + 2, s_ld, 3);
        asm volatile("cp.async.commit_group;" ::: "memory");
        MMA_GROUP(1);

        s_ld = (s_ld == 2) ? 0 : s_ld + 1;

        if (kt + 1 < NK) {
            asm volatile("cp.async.wait_group 1;" ::: "memory");
            __syncthreads();
            s_cur = (s_cur == 2) ? 0 : s_cur + 1;
            ca = sA + (uint32_t)s_cur * A_STG;
            cb = sB + (uint32_t)s_cur * A_STG;
            LDFRAG(0, ca, cb, 0);
        }
    }

    // ---- epilogue: corrected logits -> exp -> per-row partial sums ----
    int tg[4][2];
#pragma unroll
    for (int mi = 0; mi < 4; mi++)
#pragma unroll
        for (int h = 0; h < 2; h++)
            tg[mi][h] = targets[bm + wm * 64 + mi * 16 + (lane >> 2) + h * 8];

    float rs[4][2];
#pragma unroll
    for (int mi = 0; mi < 4; mi++) { rs[mi][0] = 0.f; rs[mi][1] = 0.f; }

#pragma unroll
    for (int ni = 0; ni < 8; ni++) {
#pragma unroll
        for (int j = 0; j < 2; j++) {
            int col = bn + wn * 64 + ni * 8 + ((lane & 3) << 1) + j;
            int sid = sampled[col];
            float bc = g_bcorr[col];
#pragma unroll
            for (int mi = 0; mi < 4; mi++) {
#pragma unroll
                for (int h = 0; h < 2; h++) {
                    if (sid != tg[mi][h])
                        rs[mi][h] += __expf(acc[mi][ni][h * 2 + j] + bc);
                }
            }
        }
    }

#pragma unroll
    for (int mi = 0; mi < 4; mi++) {
#pragma unroll
        for (int h = 0; h < 2; h++) {
            float v = rs[mi][h];
            v += __shfl_xor_sync(0xffffffffu, v, 1);
            v += __shfl_xor_sync(0xffffffffu, v, 2);
            if ((lane & 3) == 0)
                atomicAdd(&srow[wm * 64 + mi * 16 + (lane >> 2) + h * 8], v);
        }
    }
    __syncthreads();
    atomicAdd(&g_rowsum[bm + tid], srow[tid]);
}

// ---------------- finalize: parallel per-example loss + mean ----------------
__global__ void finalize_kernel(float* __restrict__ out) {
    __shared__ double sh[4];
    const int n = blockIdx.x * 128 + threadIdx.x;
    const int lane = threadIdx.x & 31, wid = threadIdx.x >> 5;

    float t = g_true[n];
    double local = (double)(logf(g_rowsum[n] + expf(t)) - t);
#pragma unroll
    for (int o = 16; o; o >>= 1) local += __shfl_down_sync(0xffffffffu, local, o);
    if (lane == 0) sh[wid] = local;
    __syncthreads();
    if (threadIdx.x == 0) {
        double s = sh[0] + sh[1] + sh[2] + sh[3];
        g_part[blockIdx.x] = s;
        __threadfence();
        unsigned int r = atomicAdd(&g_tick, 1u);
        if (r == 63u) {
            double tot = 0.0;
#pragma unroll 8
            for (int i = 0; i < 64; ++i) tot += g_part[i];
            out[0] = (float)(tot / (double)PN);
        }
    }
}

// ---------------- entry ----------------
extern "C" void kernel_launch(void* const* d_in, const int* in_sizes, int n_in,
                              void* d_out, int out_size) {
    const float* inputs  = (const float*)d_in[0];
    const int*   targets = (const int*)d_in[1];
    const int*   sampled = (const int*)d_in[2];
    const float* kern    = (const float*)d_in[3];
    const float* bias    = (const float*)d_in[4];
    float* out = (float*)d_out;

    static int smem_set = 0;
    if (!smem_set) {
        cudaFuncSetAttribute(gemm_exp_kernel,
                             cudaFuncAttributeMaxDynamicSharedMemorySize, SMEM_BYTES);
        smem_set = 1;
    }

    prep_kernel<<<2048, 256>>>(inputs, sampled, targets, kern, bias);

    dim3 grid(PS / 128, PN / 128);
    gemm_exp_kernel<<<grid, 128, SMEM_BYTES>>>(targets, sampled);

    finalize_kernel<<<64, 128>>>(out);
}